// round 11
// baseline (speedup 1.0000x reference)
#include <cuda_runtime.h>
#include <cstddef>

#define Nn   128
#define Lq   2048
#define NBat 2
#define Tc   32
#define NCH  64          // chunks per batch
#define NBLK 128         // co-resident blocks (1/SM)
#define NBAR 3

// Persistent device scratch (zero-initialized at module load)
__device__ float g_AdT[Nn * Nn];             // AdT[m][k] = Ad[k][m]
__device__ float g_Bd[Nn];
__device__ float g_P[Nn * Nn];               // g_P[r][c] = (Ad^32)[r][c]
__device__ float g_lfin[NBat * NCH * Nn];
__device__ float g_s[NBat * NCH * Nn];
__device__ float g_c[NBat * Lq * Nn];        // all states (2 MB)
__device__ unsigned int g_cnt[NBAR];
__device__ unsigned int g_gen[NBAR];

// Self-resetting grid barrier (generation-tagged, graph-replay safe).
// Byte-identical to the R8 version that benched clean.
__device__ __forceinline__ void gbar(int idx, unsigned* s_tmp) {
    __syncthreads();
    if (threadIdx.x == 0) {
        unsigned my = *(volatile unsigned*)&g_gen[idx];
        __threadfence();
        unsigned t = atomicAdd(&g_cnt[idx], 1u);
        if (t == NBLK - 1) {
            g_cnt[idx] = 0;
            __threadfence();
            atomicAdd(&g_gen[idx], 1u);
        } else {
            while (*(volatile unsigned*)&g_gen[idx] == my) __nanosleep(64);
        }
        __threadfence();
        *s_tmp = my;
    }
    __syncthreads();
}

__device__ __forceinline__ float scan_dot(const float* __restrict__ a,
                                          const float4* __restrict__ c4) {
    float a0 = 0.f, a1 = 0.f, a2 = 0.f, a3 = 0.f;
    #pragma unroll
    for (int jj = 0; jj < 16; jj++) {
        float4 cv = c4[jj];
        a0 = fmaf(a[4 * jj    ], cv.x, a0);
        a1 = fmaf(a[4 * jj + 1], cv.y, a1);
        a2 = fmaf(a[4 * jj + 2], cv.z, a2);
        a3 = fmaf(a[4 * jj + 3], cv.w, a3);
    }
    return (a0 + a1) + (a2 + a3);
}

// ---------------------------------------------------------------------------
// Fused prelude (R8 structure; only Stage A changed to warp-sync solve).
// 128 blocks x 256 threads, 66048 B dyn smem, 1 block/SM.
// ---------------------------------------------------------------------------
__global__ void __launch_bounds__(256, 1)
k_fused(const float* __restrict__ A, const float* __restrict__ Bv,
        const float* __restrict__ f, float* __restrict__ out) {
    extern __shared__ float sh[];            // padded 128x129 staging
    __shared__ float csh[Nn];
    __shared__ float psh[Nn];
    __shared__ float fsh[Tc];
    __shared__ unsigned s_tmp;

    const int bid = blockIdx.x, tid = threadIdx.x;
    const int k = tid & 127, h = tid >> 7, m0 = h * 64;
    const int b = bid >> 6, g = bid & 63;
    const int wid = tid >> 5, lane = tid & 31;

    // ===== Stage A: warp-synchronous forward substitution =====
    // P = I - 0.5A lower triangular. Warp 0 solves Ad column bid;
    // block 0 warp 1 solves Bd. Lane l owns rows {l, 32+l, 64+l, 96+l}.
    // Straight-line code: no spins, no block-wide barriers in the chain.
    for (int idx = tid; idx < Nn * Nn; idx += 256)
        sh[(idx >> 7) * 129 + (idx & 127)] = A[idx];
    __syncthreads();

    if (wid == 0 || (wid == 1 && bid == 0)) {
        const int c = (wid == 1) ? Nn : bid;
        float rr[4], rpiv[4], acc[4] = {0.f, 0.f, 0.f, 0.f}, sol[4];
        #pragma unroll
        for (int s = 0; s < 4; s++) {
            const int row = s * 32 + lane;
            rr[s]   = (c < Nn) ? ((row == c ? 1.f : 0.f) + 0.5f * sh[row * 129 + c])
                               : Bv[row];
            rpiv[s] = 1.f / (1.f - 0.5f * sh[row * 129 + row]);
        }
        #pragma unroll 4
        for (int j = 0; j < Nn; j++) {
            const int s = j >> 5, src = j & 31;
            float cand = (rr[s] - acc[s]) * rpiv[s];
            float xj = __shfl_sync(0xffffffffu, cand, src);
            if (lane == src) sol[s] = xj;
            #pragma unroll
            for (int s2 = 0; s2 < 4; s2++) {
                const int row = s2 * 32 + lane;
                if (row > j)
                    acc[s2] = fmaf(-0.5f * sh[row * 129 + j], xj, acc[s2]);
            }
        }
        #pragma unroll
        for (int s = 0; s < 4; s++) {
            const int row = s * 32 + lane;
            if (c < Nn) g_AdT[c * Nn + row] = sol[s];   // AdT[c][row] = Ad[row][c]
            else        g_Bd[row]           = sol[s];
        }
    }
    gbar(0, &s_tmp);

    // ===== Stage B: phase 1 — per-chunk zero-init local scan (R8) =====
    float a[64];
    #pragma unroll
    for (int j = 0; j < 64; j++) a[j] = g_AdT[(m0 + j) * Nn + k];
    const float bd = g_Bd[k];
    if (tid < Tc) fsh[tid] = f[b * Lq + g * Tc + tid];
    if (h == 0) csh[k] = 0.f;
    __syncthreads();
    {
        const float4* c4 = (const float4*)(csh + m0);
        float cn = 0.f;
        for (int d = 0; d < Tc; d++) {
            float acc = scan_dot(a, c4);
            if (h == 0) acc = fmaf(bd, fsh[d], acc);
            if (h == 1) psh[k] = acc;
            __syncthreads();
            if (h == 0) { cn = acc + psh[k]; csh[k] = cn; }
            __syncthreads();
        }
        if (h == 0) g_lfin[(b * NCH + g) * Nn + k] = cn;
    }

    // ===== Stage C: row bid of Ad^32 via v <- Ad^T v, v0 = e_bid (R8) =====
    {
        float w[64];
        #pragma unroll
        for (int j = 0; j < 64; j++) w[j] = g_AdT[k * Nn + m0 + j];  // Ad[m][k]
        __syncthreads();
        if (h == 0) csh[k] = (k == bid) ? 1.f : 0.f;
        __syncthreads();
        const float4* c4 = (const float4*)(csh + m0);
        for (int d = 0; d < 32; d++) {
            float acc = scan_dot(w, c4);
            if (h == 1) psh[k] = acc;
            __syncthreads();
            if (h == 0) csh[k] = acc + psh[k];
            __syncthreads();
        }
        if (h == 0) g_P[bid * Nn + k] = csh[k];    // Ad^32[bid][k]
    }
    gbar(1, &s_tmp);

    // ===== Stage D: phase 2 on blocks 0,1: s_{g+1} = Ad^32 s_g + lfin_g =====
    if (bid < NBat) {
        float w2[64];
        #pragma unroll
        for (int j = 0; j < 64; j++) w2[j] = g_P[k * Nn + m0 + j];   // Ad^32[k][m]
        if (h == 0) { csh[k] = 0.f; g_s[(bid * NCH) * Nn + k] = 0.f; }
        __syncthreads();
        const float4* c4 = (const float4*)(csh + m0);
        for (int gg = 1; gg < NCH; gg++) {
            float acc = scan_dot(w2, c4);
            if (h == 1) psh[k] = acc;
            __syncthreads();
            if (h == 0) {
                float cn = acc + psh[k] + g_lfin[(bid * NCH + gg - 1) * Nn + k];
                csh[k] = cn;
                g_s[(bid * NCH + gg) * Nn + k] = cn;
            }
            __syncthreads();
        }
    }
    gbar(2, &s_tmp);

    // ===== Stage E: rescan chunk from true entering state; write states =====
    {
        if (tid < Tc) fsh[tid] = f[b * Lq + g * Tc + tid];
        if (h == 0) csh[k] = g_s[(b * NCH + g) * Nn + k];
        __syncthreads();
        const float4* c4 = (const float4*)(csh + m0);
        float cn = 0.f;
        for (int d = 0; d < Tc; d++) {
            float acc = scan_dot(a, c4);
            if (h == 0) acc = fmaf(bd, fsh[d], acc);
            if (h == 1) psh[k] = acc;
            __syncthreads();
            if (h == 0) {
                cn = acc + psh[k];
                csh[k] = cn;
                g_c[(size_t)(b * Lq + g * Tc + d) * Nn + k] = cn;
            }
            __syncthreads();
        }
        if (h == 0 && g == NCH - 1) out[b * Nn + k] = cn;   // c_fin
    }
}

// ---------------------------------------------------------------------------
// Broadcast: y[b,t,n,k] = C[n]*c[b,t,k] + D*f[b,t].  4096 blocks, one (b,t).
// Proven 40 us store engine — unchanged from R8.
// ---------------------------------------------------------------------------
__global__ void k_bcast(const float* __restrict__ C, const float* __restrict__ Dv,
                        const float* __restrict__ f, float* __restrict__ out) {
    const int bt = blockIdx.x;
    const int tid = threadIdx.x, wid = tid >> 5, lane = tid & 31;
    __shared__ float csh[Nn];
    __shared__ float Csh[Nn];
    if (tid < Nn) {
        csh[tid] = g_c[(size_t)bt * Nn + tid];
        Csh[tid] = C[tid];
    }
    const float Df = Dv[0] * f[bt];
    __syncthreads();

    const float4 cv = ((const float4*)csh)[lane];
    float4* dst = (float4*)(out + 256 + ((size_t)bt << 14));
    #pragma unroll
    for (int it = 0; it < 16; it++) {
        const int n = it * 8 + wid;          // warp writes one full 512B row
        const float Cn = Csh[n];
        float4 v;
        v.x = fmaf(Cn, cv.x, Df);
        v.y = fmaf(Cn, cv.y, Df);
        v.z = fmaf(Cn, cv.z, Df);
        v.w = fmaf(Cn, cv.w, Df);
        dst[n * 32 + lane] = v;
    }
}

extern "C" void kernel_launch(void* const* d_in, const int* in_sizes, int n_in,
                              void* d_out, int out_size) {
    const float* f  = (const float*)d_in[0];
    const float* A  = (const float*)d_in[1];
    const float* Bv = (const float*)d_in[2];
    const float* C  = (const float*)d_in[3];
    const float* Dv = (const float*)d_in[4];
    float* out = (float*)d_out;

    const int smem = Nn * 129 * (int)sizeof(float);   // 66048 B
    cudaFuncSetAttribute(k_fused, cudaFuncAttributeMaxDynamicSharedMemorySize, smem);
    k_fused<<<NBLK, 256, smem>>>(A, Bv, f, out);
    k_bcast<<<NBat * Lq, 256>>>(C, Dv, f, out);
}

// round 12
// speedup vs baseline: 1.4856x; 1.4856x over previous
#include <cuda_runtime.h>
#include <cstddef>

#define Nn   128
#define Lq   2048
#define NBat 2
#define Tc   32
#define NCH  64          // chunks per batch
#define NBLK 128         // co-resident blocks (1/SM)
#define NBAR 3

// Persistent device scratch (zero-initialized at module load)
__device__ float g_AdT[Nn * Nn];             // AdT[m][k] = Ad[k][m]
__device__ float g_Bd[Nn];
__device__ float g_P[Nn * Nn];               // g_P[r][c] = (Ad^32)[r][c]
__device__ float g_lfin[NBat * NCH * Nn];
__device__ float g_s[NBat * NCH * Nn];
__device__ float g_c[NBat * Lq * Nn];        // all states (2 MB)
__device__ unsigned int g_cnt[NBAR];
__device__ unsigned int g_gen[NBAR];

// Self-resetting grid barrier (generation-tagged, graph-replay safe). Proven.
__device__ __forceinline__ void gbar(int idx, unsigned* s_tmp) {
    __syncthreads();
    if (threadIdx.x == 0) {
        unsigned my = *(volatile unsigned*)&g_gen[idx];
        __threadfence();
        unsigned t = atomicAdd(&g_cnt[idx], 1u);
        if (t == NBLK - 1) {
            g_cnt[idx] = 0;
            __threadfence();
            atomicAdd(&g_gen[idx], 1u);
        } else {
            while (*(volatile unsigned*)&g_gen[idx] == my) __nanosleep(64);
        }
        __threadfence();
        *s_tmp = my;
    }
    __syncthreads();
}

// ---- packed f32x2 helpers (ptxas never emits FFMA2 from C++) ----
__device__ __forceinline__ unsigned long long pack2(float lo, float hi) {
    unsigned long long r;
    asm("mov.b64 %0, {%1, %2};"
        : "=l"(r) : "r"(__float_as_uint(lo)), "r"(__float_as_uint(hi)));
    return r;
}
// 64-element dot: a2[32] packed matrix pairs (registers), st = 16B-aligned
// 64-float state slice in smem, read as ulonglong2 (LDS.128 -> 2x f32x2).
__device__ __forceinline__ float dot64p(const unsigned long long* __restrict__ a2,
                                        const float* __restrict__ st) {
    const ulonglong2* c2 = (const ulonglong2*)st;
    unsigned long long acc0 = 0ull, acc1 = 0ull;   // packed (0.0f, 0.0f)
    #pragma unroll
    for (int jj = 0; jj < 16; jj++) {
        ulonglong2 cv = c2[jj];
        asm("fma.rn.f32x2 %0, %1, %2, %0;" : "+l"(acc0) : "l"(a2[2 * jj    ]), "l"(cv.x));
        asm("fma.rn.f32x2 %0, %1, %2, %0;" : "+l"(acc1) : "l"(a2[2 * jj + 1]), "l"(cv.y));
    }
    unsigned lo0, hi0, lo1, hi1;
    asm("mov.b64 {%0, %1}, %2;" : "=r"(lo0), "=r"(hi0) : "l"(acc0));
    asm("mov.b64 {%0, %1}, %2;" : "=r"(lo1), "=r"(hi1) : "l"(acc1));
    return (__uint_as_float(lo0) + __uint_as_float(hi0))
         + (__uint_as_float(lo1) + __uint_as_float(hi1));
}

// ---------------------------------------------------------------------------
// Fused prelude (proven R11 structure; scan dots now FFMA2-packed).
// 128 blocks x 256 threads, 66048 B dyn smem, 1 block/SM.
// ---------------------------------------------------------------------------
__global__ void __launch_bounds__(256, 1)
k_fused(const float* __restrict__ A, const float* __restrict__ Bv,
        const float* __restrict__ f, float* __restrict__ out) {
    extern __shared__ float sh[];            // padded 128x129 staging
    __shared__ __align__(16) float csh[Nn];
    __shared__ float psh[Nn];
    __shared__ float fsh[Tc];
    __shared__ unsigned s_tmp;

    const int bid = blockIdx.x, tid = threadIdx.x;
    const int k = tid & 127, h = tid >> 7, m0 = h * 64;
    const int b = bid >> 6, g = bid & 63;
    const int wid = tid >> 5, lane = tid & 31;

    // ===== Stage A: warp-synchronous forward substitution (proven) =====
    for (int idx = tid; idx < Nn * Nn; idx += 256)
        sh[(idx >> 7) * 129 + (idx & 127)] = A[idx];
    __syncthreads();

    if (wid == 0 || (wid == 1 && bid == 0)) {
        const int c = (wid == 1) ? Nn : bid;
        float rr[4], rpiv[4], acc[4] = {0.f, 0.f, 0.f, 0.f}, sol[4];
        #pragma unroll
        for (int s = 0; s < 4; s++) {
            const int row = s * 32 + lane;
            rr[s]   = (c < Nn) ? ((row == c ? 1.f : 0.f) + 0.5f * sh[row * 129 + c])
                               : Bv[row];
            rpiv[s] = 1.f / (1.f - 0.5f * sh[row * 129 + row]);
        }
        #pragma unroll 4
        for (int j = 0; j < Nn; j++) {
            const int s = j >> 5, src = j & 31;
            float cand = (rr[s] - acc[s]) * rpiv[s];
            float xj = __shfl_sync(0xffffffffu, cand, src);
            if (lane == src) sol[s] = xj;
            #pragma unroll
            for (int s2 = 0; s2 < 4; s2++) {
                const int row = s2 * 32 + lane;
                if (row > j)
                    acc[s2] = fmaf(-0.5f * sh[row * 129 + j], xj, acc[s2]);
            }
        }
        #pragma unroll
        for (int s = 0; s < 4; s++) {
            const int row = s * 32 + lane;
            if (c < Nn) g_AdT[c * Nn + row] = sol[s];
            else        g_Bd[row]           = sol[s];
        }
    }
    gbar(0, &s_tmp);

    // ===== Stage B: phase 1 — per-chunk zero-init local scan (FFMA2) =====
    unsigned long long a2[32];               // packed AdT[(m0+2j..+1)][k]
    #pragma unroll
    for (int j = 0; j < 32; j++)
        a2[j] = pack2(g_AdT[(m0 + 2 * j) * Nn + k], g_AdT[(m0 + 2 * j + 1) * Nn + k]);
    const float bd = g_Bd[k];
    if (tid < Tc) fsh[tid] = f[b * Lq + g * Tc + tid];
    if (h == 0) csh[k] = 0.f;
    __syncthreads();
    {
        float cn = 0.f;
        for (int d = 0; d < Tc; d++) {
            float acc = dot64p(a2, csh + m0);
            if (h == 0) acc = fmaf(bd, fsh[d], acc);
            if (h == 1) psh[k] = acc;
            __syncthreads();
            if (h == 0) { cn = acc + psh[k]; csh[k] = cn; }
            __syncthreads();
        }
        if (h == 0) g_lfin[(b * NCH + g) * Nn + k] = cn;
    }

    // ===== Stage C: row bid of Ad^32 via v <- Ad^T v, v0 = e_bid (FFMA2) =====
    {
        unsigned long long w2[32];           // packed AdT[k][m0+2j..+1] (row k)
        #pragma unroll
        for (int j = 0; j < 32; j++)
            w2[j] = pack2(g_AdT[k * Nn + m0 + 2 * j], g_AdT[k * Nn + m0 + 2 * j + 1]);
        __syncthreads();
        if (h == 0) csh[k] = (k == bid) ? 1.f : 0.f;
        __syncthreads();
        for (int d = 0; d < 32; d++) {
            float acc = dot64p(w2, csh + m0);
            if (h == 1) psh[k] = acc;
            __syncthreads();
            if (h == 0) csh[k] = acc + psh[k];
            __syncthreads();
        }
        if (h == 0) g_P[bid * Nn + k] = csh[k];    // Ad^32[bid][k]
    }
    gbar(1, &s_tmp);

    // ===== Stage D: phase 2 on blocks 0,1: s_{g+1} = Ad^32 s_g + lfin_g =====
    if (bid < NBat) {
        unsigned long long p2[32];           // packed Ad^32[k][m0+2j..+1]
        #pragma unroll
        for (int j = 0; j < 32; j++)
            p2[j] = pack2(g_P[k * Nn + m0 + 2 * j], g_P[k * Nn + m0 + 2 * j + 1]);
        if (h == 0) { csh[k] = 0.f; g_s[(bid * NCH) * Nn + k] = 0.f; }
        __syncthreads();
        for (int gg = 1; gg < NCH; gg++) {
            float acc = dot64p(p2, csh + m0);
            if (h == 1) psh[k] = acc;
            __syncthreads();
            if (h == 0) {
                float cn = acc + psh[k] + g_lfin[(bid * NCH + gg - 1) * Nn + k];
                csh[k] = cn;
                g_s[(bid * NCH + gg) * Nn + k] = cn;
            }
            __syncthreads();
        }
    }
    gbar(2, &s_tmp);

    // ===== Stage E: rescan chunk from true entering state; write states =====
    {
        if (tid < Tc) fsh[tid] = f[b * Lq + g * Tc + tid];
        if (h == 0) csh[k] = g_s[(b * NCH + g) * Nn + k];
        __syncthreads();
        float cn = 0.f;
        for (int d = 0; d < Tc; d++) {
            float acc = dot64p(a2, csh + m0);
            if (h == 0) acc = fmaf(bd, fsh[d], acc);
            if (h == 1) psh[k] = acc;
            __syncthreads();
            if (h == 0) {
                cn = acc + psh[k];
                csh[k] = cn;
                g_c[(size_t)(b * Lq + g * Tc + d) * Nn + k] = cn;
            }
            __syncthreads();
        }
        if (h == 0 && g == NCH - 1) out[b * Nn + k] = cn;   // c_fin
    }
}

// ---------------------------------------------------------------------------
// Broadcast: y[b,t,n,k] = C[n]*c[b,t,k] + D*f[b,t].  4096 blocks, one (b,t).
// Proven store engine — unchanged.
// ---------------------------------------------------------------------------
__global__ void k_bcast(const float* __restrict__ C, const float* __restrict__ Dv,
                        const float* __restrict__ f, float* __restrict__ out) {
    const int bt = blockIdx.x;
    const int tid = threadIdx.x, wid = tid >> 5, lane = tid & 31;
    __shared__ __align__(16) float csh[Nn];
    __shared__ float Csh[Nn];
    if (tid < Nn) {
        csh[tid] = g_c[(size_t)bt * Nn + tid];
        Csh[tid] = C[tid];
    }
    const float Df = Dv[0] * f[bt];
    __syncthreads();

    const float4 cv = ((const float4*)csh)[lane];
    float4* dst = (float4*)(out + 256 + ((size_t)bt << 14));
    #pragma unroll
    for (int it = 0; it < 16; it++) {
        const int n = it * 8 + wid;          // warp writes one full 512B row
        const float Cn = Csh[n];
        float4 v;
        v.x = fmaf(Cn, cv.x, Df);
        v.y = fmaf(Cn, cv.y, Df);
        v.z = fmaf(Cn, cv.z, Df);
        v.w = fmaf(Cn, cv.w, Df);
        dst[n * 32 + lane] = v;
    }
}

extern "C" void kernel_launch(void* const* d_in, const int* in_sizes, int n_in,
                              void* d_out, int out_size) {
    const float* f  = (const float*)d_in[0];
    const float* A  = (const float*)d_in[1];
    const float* Bv = (const float*)d_in[2];
    const float* C  = (const float*)d_in[3];
    const float* Dv = (const float*)d_in[4];
    float* out = (float*)d_out;

    const int smem = Nn * 129 * (int)sizeof(float);   // 66048 B
    cudaFuncSetAttribute(k_fused, cudaFuncAttributeMaxDynamicSharedMemorySize, smem);
    k_fused<<<NBLK, 256, smem>>>(A, Bv, f, out);
    k_bcast<<<NBat * Lq, 256>>>(C, Dv, f, out);
}